// round 6
// baseline (speedup 1.0000x reference)
#include <cuda_runtime.h>
#include <cstdint>

#define B_      8
#define NV_     8192
#define E_      32768
#define KSPLIT  16
#define KRANGE  (E_ / KSPLIT)     // 2048
#define CHK     128               // A-chunk (e) staged in smem
#define NCHUNK  (KRANGE / CHK)    // 16
#define VT      256               // vertices per CTA
#define NVT     (NV_ / VT)        // 32
#define SAPAD   132               // smem A row stride (floats) -> conflict-free frags

// Scratch (device globals: allocation-free kernel_launch)
__device__ float g_Mt[24 * E_];                   // M transposed: [cb][e]  (3 MB)
__device__ float g_part[KSPLIT * 24 * NV_];       // K-split partials [ks][cb][n] (12.6 MB)

__device__ __forceinline__ uint32_t tf32r(float f) {
    uint32_t r;
    asm("cvt.rna.tf32.f32 %0, %1;" : "=r"(r) : "f"(f));
    return r;
}

// ---------------- Kernel 1: per-edge XPBD solve, thread per (b, e) ----------------
__global__ void edge_kernel(const float* __restrict__ Vp, const float* __restrict__ L,
                            const float* __restrict__ Vw, const float* __restrict__ Vc,
                            const int* __restrict__ Cd, const float* __restrict__ C0,
                            float* __restrict__ Lnew) {
    int idx = blockIdx.x * blockDim.x + threadIdx.x;   // b*E_ + e
    int b = idx >> 15;            // E_ = 2^15
    int e = idx & (E_ - 1);
    int i = Cd[2 * e];
    int j = Cd[2 * e + 1];
    float c0 = C0[e];
    const float* pi = Vp + ((size_t)b * NV_ + i) * 3;
    const float* pj = Vp + ((size_t)b * NV_ + j) * 3;
    float nx = pi[0] - pj[0];
    float ny = pi[1] - pj[1];
    float nz = pi[2] - pj[2];
    float D = sqrtf(nx * nx + ny * ny + nz * nz);
    float C = D - c0;
    float invD = 1.0f / (D + 1e-8f);
    float A = Vc[b];
    float S = Vw[b * NV_ + i] + Vw[b * NV_ + j];
    if (S == 0.0f) S = __int_as_float(0x7f800000);
    float Lbe = L[b * E_ + e];
    float Ld = (-C - A * Lbe) / (S + A);
    Lnew[b * E_ + e] = Lbe + Ld;
    float s = Ld * invD;
    g_Mt[(0 * 8 + b) * E_ + e] = s * nx;
    g_Mt[(1 * 8 + b) * E_ + e] = s * ny;
    g_Mt[(2 * 8 + b) * E_ + e] = s * nz;
}

// ---------------- tf32 HMMA helper ----------------
__device__ __forceinline__ void mma_tf32(float* c, uint32_t a0, uint32_t a1, uint32_t a2,
                                         uint32_t a3, uint32_t b0, uint32_t b1) {
    asm volatile(
        "mma.sync.aligned.m16n8k8.row.col.f32.tf32.tf32.f32 "
        "{%0,%1,%2,%3}, {%4,%5,%6,%7}, {%8,%9}, {%0,%1,%2,%3};"
        : "+f"(c[0]), "+f"(c[1]), "+f"(c[2]), "+f"(c[3])
        : "r"(a0), "r"(a1), "r"(a2), "r"(a3), "r"(b0), "r"(b1));
}

// ---------------- Kernel 2: tf32 HMMA GEMM, vectorized B via n-tile interleave ----
// out[m=cb (24->32 padded)][n=vertex] += A[m][k=e] * B[k][n]
//   A = g_Mt (smem-staged, rna-rounded), B = Cmtx streamed global->LDG.128 frags
//   Warp n-tile nt covers global columns { vw + 4*j + nt : j=0..7 }  (interleaved!)
__global__ void __launch_bounds__(256) gemm_kernel(const float* __restrict__ Cmtx) {
    __shared__ float sA[32 * SAPAD];

    int tid = threadIdx.x;
    int wid = tid >> 5;
    int lane = tid & 31;
    int vt = blockIdx.x;
    int ks = blockIdx.y;
    int vw = vt * VT + wid * 32;                 // this warp's 32 vertices
    int ebase0 = ks * KRANGE;

    // zero A pad rows 24..31 once (never written again)
    for (int f = tid; f < 8 * SAPAD; f += 256) sA[24 * SAPAD + f] = 0.0f;

    float acc[2][4][4];
#pragma unroll
    for (int mt = 0; mt < 2; mt++)
#pragma unroll
        for (int nt = 0; nt < 4; nt++)
#pragma unroll
            for (int k = 0; k < 4; k++) acc[mt][nt][k] = 0.0f;

    int kq = lane & 3;     // k within quad
    int g  = lane >> 2;    // group id (fragment row/col index)

#pragma unroll 1
    for (int chunk = 0; chunk < NCHUNK; chunk++) {
        int eb = ebase0 + chunk * CHK;
        __syncthreads();
        // stage A chunk: rows 0..23, CHK e-columns, rna-rounded to tf32
#pragma unroll
        for (int it = 0; it < 3; it++) {
            int f = tid + it * 256;              // 0..767
            int row = f >> 5, q = f & 31;
            float4 v = *reinterpret_cast<const float4*>(g_Mt + (size_t)row * E_ + eb + q * 4);
            uint4 t = make_uint4(tf32r(v.x), tf32r(v.y), tf32r(v.z), tf32r(v.w));
            *reinterpret_cast<uint4*>(sA + row * SAPAD + q * 4) = t;
        }
        __syncthreads();

#pragma unroll 4
        for (int s = 0; s < CHK / 8; s++) {
            // B fragments: one LDG.128 covers all 4 n-tiles (cols vw+4g .. vw+4g+3)
            const float* bp = Cmtx + (size_t)(eb + s * 8 + kq) * NV_ + vw + 4 * g;
            float4 b0v = __ldcs(reinterpret_cast<const float4*>(bp));
            float4 b1v = __ldcs(reinterpret_cast<const float4*>(bp + 4 * (size_t)NV_));
            uint32_t b0[4] = {tf32r(b0v.x), tf32r(b0v.y), tf32r(b0v.z), tf32r(b0v.w)};
            uint32_t b1[4] = {tf32r(b1v.x), tf32r(b1v.y), tf32r(b1v.z), tf32r(b1v.w)};
            // A fragments from smem (already tf32-rounded)
            int koff = s * 8 + kq;
            uint32_t a[2][4];
#pragma unroll
            for (int mt = 0; mt < 2; mt++) {
                const float* ap = sA + (mt * 16 + g) * SAPAD + koff;
                a[mt][0] = __float_as_uint(ap[0]);
                a[mt][1] = __float_as_uint(ap[8 * SAPAD]);
                a[mt][2] = __float_as_uint(ap[4]);
                a[mt][3] = __float_as_uint(ap[8 * SAPAD + 4]);
            }
#pragma unroll
            for (int mt = 0; mt < 2; mt++)
#pragma unroll
                for (int nt = 0; nt < 4; nt++)
                    mma_tf32(acc[mt][nt], a[mt][0], a[mt][1], a[mt][2], a[mt][3],
                             b0[nt], b1[nt]);
        }
    }

    // store partials. D-tile nt col c -> global v = vw + 4*c + nt, so gathering one
    // d-slot across nt = 4 consecutive vertices -> STG.128.
    // lane holds: d0,d1 rows g (cb=g | 16+g), cols 2kq, 2kq+1 ; d2,d3 rows g+8.
    float* pb = g_part + (size_t)ks * 24 * NV_;
    int v0 = vw + 8 * kq;
    {
        float4 q0 = make_float4(acc[0][0][0], acc[0][1][0], acc[0][2][0], acc[0][3][0]);
        float4 q1 = make_float4(acc[0][0][1], acc[0][1][1], acc[0][2][1], acc[0][3][1]);
        float4 q2 = make_float4(acc[0][0][2], acc[0][1][2], acc[0][2][2], acc[0][3][2]);
        float4 q3 = make_float4(acc[0][0][3], acc[0][1][3], acc[0][2][3], acc[0][3][3]);
        *reinterpret_cast<float4*>(pb + (size_t)g * NV_ + v0)           = q0;
        *reinterpret_cast<float4*>(pb + (size_t)g * NV_ + v0 + 4)       = q1;
        *reinterpret_cast<float4*>(pb + (size_t)(g + 8) * NV_ + v0)     = q2;
        *reinterpret_cast<float4*>(pb + (size_t)(g + 8) * NV_ + v0 + 4) = q3;
        float4 r0 = make_float4(acc[1][0][0], acc[1][1][0], acc[1][2][0], acc[1][3][0]);
        float4 r1 = make_float4(acc[1][0][1], acc[1][1][1], acc[1][2][1], acc[1][3][1]);
        *reinterpret_cast<float4*>(pb + (size_t)(g + 16) * NV_ + v0)     = r0;
        *reinterpret_cast<float4*>(pb + (size_t)(g + 16) * NV_ + v0 + 4) = r1;
        // rows 24..31 (mt1 d2,d3) are padding: dropped
    }
}

// ---------------- Kernel 3: reduce K-split partials + epilogue ----------------
__global__ void final_kernel(const float* __restrict__ Vp, const float* __restrict__ Vw,
                             float* __restrict__ out) {
    int t = blockIdx.x * blockDim.x + threadIdx.x;   // cb*NV_ + n
    if (t >= 24 * NV_) return;
    int cb = t >> 13;            // NV_ = 2^13
    int n = t & (NV_ - 1);
    float s = 0.0f;
#pragma unroll
    for (int k = 0; k < KSPLIT; k++) s += g_part[(size_t)k * 24 * NV_ + t];
    int c = cb >> 3, b = cb & 7;
    size_t oidx = ((size_t)b * NV_ + n) * 3 + c;
    out[oidx] = Vp[oidx] + Vw[b * NV_ + n] * s;
}

extern "C" void kernel_launch(void* const* d_in, const int* in_sizes, int n_in,
                              void* d_out, int out_size) {
    const float* Vp = (const float*)d_in[0];   // (B, NV, 3)
    const float* L  = (const float*)d_in[1];   // (B, E, 1)
    const float* Vw = (const float*)d_in[2];   // (B, NV, 1)
    const float* Vc = (const float*)d_in[3];   // (B, 1, 1)
    const int*   Cd = (const int*)d_in[4];     // (E, 2)
    const float* C0 = (const float*)d_in[5];   // (E, 1)
    const float* Cm = (const float*)d_in[6];   // (E, NV)

    float* out = (float*)d_out;
    float* Lnew = out + (size_t)B_ * NV_ * 3;

    edge_kernel<<<(B_ * E_) / 256, 256>>>(Vp, L, Vw, Vc, Cd, C0, Lnew);
    gemm_kernel<<<dim3(NVT, KSPLIT), 256>>>(Cm);
    final_kernel<<<(24 * NV_ + 255) / 256, 256>>>(Vp, Vw, out);
}